// round 6
// baseline (speedup 1.0000x reference)
#include <cuda_runtime.h>
#include <cuda_bf16.h>
#include <math.h>
#include <stdint.h>

#define D_IN   1024
#define D_H    2048
#define BATCH  256
#define D_OUT  1000
#define EPSV   1e-12f
#define STEPS  30

// ---- bf16 GEMM smem geometry (x_proj / head path) ----
#define ROW_B      144
#define TILE_A_HI  0
#define TILE_A_LO  9216
#define TILE_B_HI  18432
#define TILE_B_LO  27648
#define STAGE_BYTES 36864
#define SMEM_BYTES  (2 * STAGE_BYTES)

// ---- int8 step GEMM smem geometry: 4 tiles of 64 rows x 128B, pad to 144B ----
#define I8_ROW   144
#define I8_A1    0
#define I8_A2    9216
#define I8_B1    18432
#define I8_B2    27648
#define I8_STAGE 36864
#define I8_SMEM  73728

// ---------------- device scratch (no allocations allowed) ----------------
__device__ float g_t[D_IN];
__device__ float g_s[D_H];
__device__ float g_scal[4];            // [1] = 1/sigma
__device__ float g_xproj[BATCH * D_H];
__device__ float g_hA[BATCH * D_H];
__device__ float g_hB[BATCH * D_H];

// bf16 hi/lo splits (x_proj + head path only)
__device__ __nv_bfloat16 g_Winhi[D_H * D_IN], g_Winlo[D_H * D_IN];
__device__ __nv_bfloat16 g_Hdhi[D_OUT * D_H], g_Hdlo[D_OUT * D_H];
__device__ __nv_bfloat16 g_xhi[BATCH * D_IN], g_xlo[BATCH * D_IN];
__device__ __nv_bfloat16 g_hhi[BATCH * D_H], g_hlo[BATCH * D_H];

// int8 dual-limb weights + h ping-pong
__device__ signed char g_W0q1[D_H * D_H], g_W0q2[D_H * D_H];
__device__ signed char g_W1q1[D_H * D_H], g_W1q2[D_H * D_H];
__device__ signed char g_W2q1[D_H * D_H], g_W2q2[D_H * D_H];
__device__ signed char g_hq1A[BATCH * D_H], g_hq2A[BATCH * D_H];
__device__ signed char g_hq1B[BATCH * D_H], g_hq2B[BATCH * D_H];

// ---------------- portable PTX helpers (sm_80+) ----------------
__device__ __forceinline__ uint32_t smem_u32(const void* p) {
    uint32_t a;
    asm("{ .reg .u64 t; cvta.to.shared.u64 t, %1; cvt.u32.u64 %0, t; }" : "=r"(a) : "l"(p));
    return a;
}
#define CP16(dst, src) asm volatile("cp.async.cg.shared.global [%0], [%1], 16;" :: "r"(dst), "l"(src))
#define CP_COMMIT()    asm volatile("cp.async.commit_group;" ::: "memory")
#define CP_WAIT(n)     asm volatile("cp.async.wait_group %0;" :: "n"(n) : "memory")

__device__ __forceinline__ void ldsm4(uint32_t* r, uint32_t addr) {
    asm volatile("ldmatrix.sync.aligned.m8n8.x4.shared.b16 {%0,%1,%2,%3}, [%4];"
        : "=r"(r[0]), "=r"(r[1]), "=r"(r[2]), "=r"(r[3]) : "r"(addr));
}
__device__ __forceinline__ void mma_bf16(float* c, const uint32_t* a, const uint32_t* b) {
    asm volatile("mma.sync.aligned.m16n8k16.row.col.f32.bf16.bf16.f32 "
        "{%0,%1,%2,%3}, {%4,%5,%6,%7}, {%8,%9}, {%0,%1,%2,%3};"
        : "+f"(c[0]), "+f"(c[1]), "+f"(c[2]), "+f"(c[3])
        : "r"(a[0]), "r"(a[1]), "r"(a[2]), "r"(a[3]), "r"(b[0]), "r"(b[1]));
}
__device__ __forceinline__ void mma_i8(int* c, const uint32_t* a, const uint32_t* b) {
    asm volatile("mma.sync.aligned.m16n8k32.row.col.s32.s8.s8.s32 "
        "{%0,%1,%2,%3}, {%4,%5,%6,%7}, {%8,%9}, {%0,%1,%2,%3};"
        : "+r"(c[0]), "+r"(c[1]), "+r"(c[2]), "+r"(c[3])
        : "r"(a[0]), "r"(a[1]), "r"(a[2]), "r"(a[3]), "r"(b[0]), "r"(b[1]));
}

// ---------------- small kernels ----------------
__global__ void zero_kernel(float* p, int n) {
    int i = blockIdx.x * blockDim.x + threadIdx.x;
    if (i < n) p[i] = 0.0f;
}
__global__ void split_kernel(const float* __restrict__ src,
                             __nv_bfloat16* __restrict__ hi,
                             __nv_bfloat16* __restrict__ lo, int n) {
    int i = blockIdx.x * blockDim.x + threadIdx.x;
    if (i >= n) return;
    float a = src[i];
    __nv_bfloat16 h = __float2bfloat16(a);
    hi[i] = h;
    lo[i] = __float2bfloat16(a - __bfloat162float(h));
}
// int8 dual-limb split: q1 = rn(a*s1), q2 = rn((a - q1/s1)*s2)
__global__ void split_i8_kernel(const float* __restrict__ src,
                                signed char* __restrict__ q1o,
                                signed char* __restrict__ q2o,
                                int n, float s1, float inv_s1, float s2) {
    int i = blockIdx.x * blockDim.x + threadIdx.x;
    if (i >= n) return;
    float a = src[i];
    int q1 = __float2int_rn(a * s1);
    float r = fmaf((float)q1, -inv_s1, a);
    int q2 = __float2int_rn(r * s2);
    q1o[i] = (signed char)q1;
    q2o[i] = (signed char)q2;
}
__global__ void matvec_t_kernel(const float* __restrict__ W, const float* __restrict__ u,
                                float* __restrict__ t) {
    int j = blockIdx.x * blockDim.x + threadIdx.x;
    if (j >= D_IN) return;
    float acc = 0.0f;
#pragma unroll 4
    for (int i = 0; i < D_H; i++) acc = fmaf(W[(size_t)i * D_IN + j], u[i], acc);
    t[j] = acc;
}
__global__ void reduce_t_kernel(const float* __restrict__ t, float* __restrict__ scal) {
    __shared__ float sh[1024];
    int tid = threadIdx.x;
    float v = t[tid];
    sh[tid] = v * v;
    __syncthreads();
    for (int o = 512; o > 0; o >>= 1) { if (tid < o) sh[tid] += sh[tid + o]; __syncthreads(); }
    if (tid == 0) scal[0] = 1.0f / (sqrtf(sh[0]) + EPSV);
}
__global__ void matvec_s_kernel(const float* __restrict__ W, const float* __restrict__ t,
                                const float* __restrict__ scal, float* __restrict__ s) {
    int gtid = blockIdx.x * blockDim.x + threadIdx.x;
    int warp = gtid >> 5, lane = gtid & 31;
    float invn = scal[0];
    for (int r = warp; r < D_H; r += 512) {
        const float* row = W + (size_t)r * D_IN;
        float acc = 0.0f;
        for (int j = lane; j < D_IN; j += 32) acc = fmaf(row[j], t[j], acc);
#pragma unroll
        for (int o = 16; o > 0; o >>= 1) acc += __shfl_xor_sync(0xffffffffu, acc, o);
        if (lane == 0) s[r] = acc * invn;
    }
}
__global__ void reduce_s_kernel(const float* __restrict__ s, float* __restrict__ scal) {
    __shared__ float sh[1024];
    int tid = threadIdx.x;
    float a = s[tid], b = s[tid + 1024];
    sh[tid] = a * a + b * b;
    __syncthreads();
    for (int o = 512; o > 0; o >>= 1) { if (tid < o) sh[tid] += sh[tid + o]; __syncthreads(); }
    if (tid == 0) { float q = sh[0]; scal[1] = (sqrtf(q) + EPSV) / q; }
}

// ================= bf16 3-pass GEMM (x_proj MODE 0, head MODE 2) =================
template <int MODE>
__device__ __forceinline__ void epi_elem(float r, int m, int n,
        const float* __restrict__ bias, float* __restrict__ outF,
        float scale, int NB, int ldOut) {
    if (MODE == 0) {
        outF[(size_t)m * ldOut + n] = fmaf(r, scale, bias[n]);
    } else {
        if (n < NB) outF[(size_t)m * ldOut + n] = r + bias[n];
    }
}

__device__ __forceinline__ void prefetch_chunk(uint32_t sb_u, char* sb_p, int k0,
        const __nv_bfloat16* __restrict__ Ahi, const __nv_bfloat16* __restrict__ Alo,
        const __nv_bfloat16* __restrict__ Bhi, const __nv_bfloat16* __restrict__ Blo,
        int K, int NB, int m0, int n0) {
    const int t = threadIdx.x;
#pragma unroll
    for (int r = 0; r < 4; r++) {
        const int idx = t + (r << 7);
        const int row = idx >> 3;
        const int c   = idx & 7;
        const uint32_t soff = (uint32_t)row * ROW_B + (c << 4);
        const size_t ga = (size_t)(m0 + row) * K + k0 + (c << 3);
        CP16(sb_u + TILE_A_HI + soff, Ahi + ga);
        CP16(sb_u + TILE_A_LO + soff, Alo + ga);
        const int gn = n0 + row;
        if (gn < NB) {
            const size_t gb = (size_t)gn * K + k0 + (c << 3);
            CP16(sb_u + TILE_B_HI + soff, Bhi + gb);
            CP16(sb_u + TILE_B_LO + soff, Blo + gb);
        } else {
            const uint4 z = make_uint4(0, 0, 0, 0);
            *reinterpret_cast<uint4*>(sb_p + TILE_B_HI + soff) = z;
            *reinterpret_cast<uint4*>(sb_p + TILE_B_LO + soff) = z;
        }
    }
}

template <int MODE>
__global__ void __launch_bounds__(128)
gemm_mma(const __nv_bfloat16* __restrict__ Ahi, const __nv_bfloat16* __restrict__ Alo,
         const __nv_bfloat16* __restrict__ Bhi, const __nv_bfloat16* __restrict__ Blo,
         const float* __restrict__ bias, float* __restrict__ outF,
         const float* __restrict__ scale_ptr, int K, int NB, int ldOut) {
    extern __shared__ char smem[];
    const uint32_t sbase = smem_u32(smem);
    const int tid  = threadIdx.x;
    const int lane = tid & 31;
    const int wid  = tid >> 5;
    const int m0 = blockIdx.y * 64;
    const int n0 = blockIdx.x * 64;
    const int wm = (wid >> 1) << 5;
    const int wn = (wid & 1) << 5;
    const int NC = K >> 6;

    const int arow  = (lane & 7) | (((lane >> 3) & 1) << 3);
    const int akoff = ((lane >> 4) & 1) << 3;
    const int brow  = (lane & 7) | (((lane >> 4) & 1) << 3);
    const int bkoff = ((lane >> 3) & 1) << 3;

    float acc[2][4][4] = {};

    prefetch_chunk(sbase, smem, 0, Ahi, Alo, Bhi, Blo, K, NB, m0, n0);
    CP_COMMIT();

    for (int c = 0; c < NC; c++) {
        if (c + 1 < NC) {
            const int ns = (c + 1) & 1;
            prefetch_chunk(sbase + ns * STAGE_BYTES, smem + ns * STAGE_BYTES,
                           (c + 1) << 6, Ahi, Alo, Bhi, Blo, K, NB, m0, n0);
            CP_COMMIT();
            CP_WAIT(1);
        } else {
            CP_WAIT(0);
        }
        __syncthreads();

        const uint32_t st = sbase + (c & 1) * STAGE_BYTES;
#pragma unroll
        for (int kk = 0; kk < 4; kk++) {
            const int k0 = kk << 4;
            uint32_t ah[2][4], al[2][4], bh[2][4], bl[2][4];
#pragma unroll
            for (int a = 0; a < 2; a++) {
                const uint32_t off = (uint32_t)(wm + (a << 4) + arow) * ROW_B +
                                     ((k0 + akoff) << 1);
                ldsm4(ah[a], st + TILE_A_HI + off);
                ldsm4(al[a], st + TILE_A_LO + off);
            }
#pragma unroll
            for (int b = 0; b < 2; b++) {
                const uint32_t off = (uint32_t)(wn + (b << 4) + brow) * ROW_B +
                                     ((k0 + bkoff) << 1);
                ldsm4(bh[b], st + TILE_B_HI + off);
                ldsm4(bl[b], st + TILE_B_LO + off);
            }
#pragma unroll
            for (int a = 0; a < 2; a++)
#pragma unroll
                for (int j = 0; j < 4; j++)
                    mma_bf16(acc[a][j], ah[a], &bh[j >> 1][(j & 1) << 1]);
#pragma unroll
            for (int a = 0; a < 2; a++)
#pragma unroll
                for (int j = 0; j < 4; j++)
                    mma_bf16(acc[a][j], ah[a], &bl[j >> 1][(j & 1) << 1]);
#pragma unroll
            for (int a = 0; a < 2; a++)
#pragma unroll
                for (int j = 0; j < 4; j++)
                    mma_bf16(acc[a][j], al[a], &bh[j >> 1][(j & 1) << 1]);
        }
        __syncthreads();
    }

    const float scale = (MODE == 0) ? *scale_ptr : 1.0f;
    const int g  = lane >> 2;
    const int i2 = (lane & 3) << 1;
#pragma unroll
    for (int a = 0; a < 2; a++)
#pragma unroll
        for (int j = 0; j < 4; j++)
#pragma unroll
            for (int e = 0; e < 4; e++) {
                const int m = m0 + wm + (a << 4) + g + ((e >> 1) << 3);
                const int n = n0 + wn + (j << 3) + i2 + (e & 1);
                epi_elem<MODE>(acc[a][j][e], m, n, bias, outF, scale, NB, ldOut);
            }
}

// ================= int8 dual-limb step GEMM =================
// pre = xproj + (Smain*2^-18 + Scross*2^-25) + bias;  hn = 0.5*hold + 0.5*tanh(pre)
// writes hn (fp32) and re-quantized limbs q1 = rn(hn*2^6), q2 = rn((hn-q1/2^6)*2^13)
__device__ __forceinline__ void prefetch_i8(uint32_t sb_u, int k0,
        const signed char* __restrict__ A1, const signed char* __restrict__ A2,
        const signed char* __restrict__ W1, const signed char* __restrict__ W2,
        int m0, int n0) {
    const int t = threadIdx.x;
#pragma unroll
    for (int r = 0; r < 4; r++) {
        const int idx = t + (r << 7);
        const int row = idx >> 3;
        const int c   = idx & 7;
        const uint32_t soff = (uint32_t)row * I8_ROW + (c << 4);
        const size_t ga = (size_t)(m0 + row) * D_H + k0 + (c << 4);
        const size_t gb = (size_t)(n0 + row) * D_H + k0 + (c << 4);
        CP16(sb_u + I8_A1 + soff, A1 + ga);
        CP16(sb_u + I8_A2 + soff, A2 + ga);
        CP16(sb_u + I8_B1 + soff, W1 + gb);
        CP16(sb_u + I8_B2 + soff, W2 + gb);
    }
}

__global__ void __launch_bounds__(128)
gemm_step_i8(const signed char* __restrict__ A1, const signed char* __restrict__ A2,
             const signed char* __restrict__ W1, const signed char* __restrict__ W2,
             const float* __restrict__ bias,
             const float* __restrict__ xproj, const float* __restrict__ hold,
             float* __restrict__ outF,
             signed char* __restrict__ outQ1, signed char* __restrict__ outQ2) {
    extern __shared__ char smem[];
    const uint32_t sbase = smem_u32(smem);
    const int tid  = threadIdx.x;
    const int lane = tid & 31;
    const int wid  = tid >> 5;
    const int m0 = blockIdx.y * 64;
    const int n0 = blockIdx.x * 64;
    const int wm = (wid >> 1) << 5;
    const int wn = (wid & 1) << 5;
    const int NC = D_H / 128;     // 16 chunks of 128 i8

    const int arow  = (lane & 7) | (((lane >> 3) & 1) << 3);
    const int akoff = ((lane >> 4) & 1) << 3;   // in b16 units
    const int brow  = (lane & 7) | (((lane >> 4) & 1) << 3);
    const int bkoff = ((lane >> 3) & 1) << 3;

    int accm[2][4][4] = {};
    int accx[2][4][4] = {};

    prefetch_i8(sbase, 0, A1, A2, W1, W2, m0, n0);
    CP_COMMIT();

    for (int c = 0; c < NC; c++) {
        if (c + 1 < NC) {
            const int ns = (c + 1) & 1;
            prefetch_i8(sbase + ns * I8_STAGE, (c + 1) << 7, A1, A2, W1, W2, m0, n0);
            CP_COMMIT();
            CP_WAIT(1);
        } else {
            CP_WAIT(0);
        }
        __syncthreads();

        const uint32_t st = sbase + (c & 1) * I8_STAGE;
#pragma unroll
        for (int kk = 0; kk < 4; kk++) {       // kk spans 32 i8 = 16 b16
            const int k0 = kk << 4;            // b16 units
            uint32_t a1[2][4], a2[2][4], b1[2][4], b2[2][4];
#pragma unroll
            for (int a = 0; a < 2; a++) {
                const uint32_t off = (uint32_t)(wm + (a << 4) + arow) * I8_ROW +
                                     ((k0 + akoff) << 1);
                ldsm4(a1[a], st + I8_A1 + off);
                ldsm4(a2[a], st + I8_A2 + off);
            }
#pragma unroll
            for (int b = 0; b < 2; b++) {
                const uint32_t off = (uint32_t)(wn + (b << 4) + brow) * I8_ROW +
                                     ((k0 + bkoff) << 1);
                ldsm4(b1[b], st + I8_B1 + off);
                ldsm4(b2[b], st + I8_B2 + off);
            }
            // main: A1*W1 (scale 2^-18)
#pragma unroll
            for (int a = 0; a < 2; a++)
#pragma unroll
                for (int j = 0; j < 4; j++)
                    mma_i8(accm[a][j], a1[a], &b1[j >> 1][(j & 1) << 1]);
            // cross: A1*W2 + A2*W1 (both scale 2^-25, shared accumulator)
#pragma unroll
            for (int a = 0; a < 2; a++)
#pragma unroll
                for (int j = 0; j < 4; j++)
                    mma_i8(accx[a][j], a1[a], &b2[j >> 1][(j & 1) << 1]);
#pragma unroll
            for (int a = 0; a < 2; a++)
#pragma unroll
                for (int j = 0; j < 4; j++)
                    mma_i8(accx[a][j], a2[a], &b1[j >> 1][(j & 1) << 1]);
        }
        __syncthreads();
    }

    const float scm = 3.814697265625e-06f;       // 2^-18
    const float scx = 2.9802322387695312e-08f;   // 2^-25
    const int g  = lane >> 2;
    const int i2 = (lane & 3) << 1;
#pragma unroll
    for (int a = 0; a < 2; a++)
#pragma unroll
        for (int j = 0; j < 4; j++)
#pragma unroll
            for (int e = 0; e < 4; e++) {
                const int m = m0 + wm + (a << 4) + g + ((e >> 1) << 3);
                const int n = n0 + wn + (j << 3) + i2 + (e & 1);
                const size_t idx = (size_t)m * D_H + n;
                const float r = (float)accm[a][j][e] * scm + (float)accx[a][j][e] * scx;
                const float pre = xproj[idx] + r + bias[n];
                const float hn = 0.5f * hold[idx] + 0.5f * tanhf(pre);
                outF[idx] = hn;
                const int q1 = __float2int_rn(hn * 64.0f);
                const float rr = fmaf((float)q1, -0.015625f, hn);
                const int q2 = __float2int_rn(rr * 8192.0f);
                outQ1[idx] = (signed char)q1;
                outQ2[idx] = (signed char)q2;
            }
}

// ---------------- host ----------------
extern "C" void kernel_launch(void* const* d_in, const int* in_sizes, int n_in,
                              void* d_out, int out_size) {
    const float* x     = (const float*)d_in[0];
    const float* Winw  = (const float*)d_in[1];
    const float* Winb  = (const float*)d_in[2];
    const float* u     = (const float*)d_in[3];
    const float* W0    = (const float*)d_in[4];
    const float* b0    = (const float*)d_in[5];
    const float* W1    = (const float*)d_in[6];
    const float* b1    = (const float*)d_in[7];
    const float* W2    = (const float*)d_in[8];
    const float* b2    = (const float*)d_in[9];
    const float* headw = (const float*)d_in[10];
    const float* headb = (const float*)d_in[11];
    float* out = (float*)d_out;

    float *t, *s, *scal, *xp, *hA, *hB;
    cudaGetSymbolAddress((void**)&t, g_t);
    cudaGetSymbolAddress((void**)&s, g_s);
    cudaGetSymbolAddress((void**)&scal, g_scal);
    cudaGetSymbolAddress((void**)&xp, g_xproj);
    cudaGetSymbolAddress((void**)&hA, g_hA);
    cudaGetSymbolAddress((void**)&hB, g_hB);
    __nv_bfloat16 *Winh, *Winl, *Hdh, *Hdl, *xh, *xl, *hh, *hl;
    cudaGetSymbolAddress((void**)&Winh, g_Winhi); cudaGetSymbolAddress((void**)&Winl, g_Winlo);
    cudaGetSymbolAddress((void**)&Hdh, g_Hdhi);   cudaGetSymbolAddress((void**)&Hdl, g_Hdlo);
    cudaGetSymbolAddress((void**)&xh, g_xhi);     cudaGetSymbolAddress((void**)&xl, g_xlo);
    cudaGetSymbolAddress((void**)&hh, g_hhi);     cudaGetSymbolAddress((void**)&hl, g_hlo);
    signed char *W0q1, *W0q2, *W1q1, *W1q2, *W2q1, *W2q2, *hq1A, *hq2A, *hq1B, *hq2B;
    cudaGetSymbolAddress((void**)&W0q1, g_W0q1); cudaGetSymbolAddress((void**)&W0q2, g_W0q2);
    cudaGetSymbolAddress((void**)&W1q1, g_W1q1); cudaGetSymbolAddress((void**)&W1q2, g_W1q2);
    cudaGetSymbolAddress((void**)&W2q1, g_W2q1); cudaGetSymbolAddress((void**)&W2q2, g_W2q2);
    cudaGetSymbolAddress((void**)&hq1A, g_hq1A); cudaGetSymbolAddress((void**)&hq2A, g_hq2A);
    cudaGetSymbolAddress((void**)&hq1B, g_hq1B); cudaGetSymbolAddress((void**)&hq2B, g_hq2B);

    cudaFuncSetAttribute(gemm_mma<0>, cudaFuncAttributeMaxDynamicSharedMemorySize, SMEM_BYTES);
    cudaFuncSetAttribute(gemm_mma<2>, cudaFuncAttributeMaxDynamicSharedMemorySize, SMEM_BYTES);
    cudaFuncSetAttribute(gemm_step_i8, cudaFuncAttributeMaxDynamicSharedMemorySize, I8_SMEM);

    // h0 = 0: fp32 + int8 limbs
    zero_kernel<<<(BATCH * D_H + 255) / 256, 256>>>(hA, BATCH * D_H);
    zero_kernel<<<(BATCH * D_H / 4 + 255) / 256, 256>>>((float*)hq1A, BATCH * D_H / 4);
    zero_kernel<<<(BATCH * D_H / 4 + 255) / 256, 256>>>((float*)hq2A, BATCH * D_H / 4);

    // weight int8 dual-limb splits: W1=rn(W*2^12), W2=rn((W-W1/2^12)*2^19)
    const int TB = 256;
    const float S1 = 4096.0f, IS1 = 1.0f / 4096.0f, S2 = 524288.0f;
    split_i8_kernel<<<(D_H * D_H + TB - 1) / TB, TB>>>(W0, W0q1, W0q2, D_H * D_H, S1, IS1, S2);
    split_i8_kernel<<<(D_H * D_H + TB - 1) / TB, TB>>>(W1, W1q1, W1q2, D_H * D_H, S1, IS1, S2);
    split_i8_kernel<<<(D_H * D_H + TB - 1) / TB, TB>>>(W2, W2q1, W2q2, D_H * D_H, S1, IS1, S2);

    // bf16 splits for x_proj + head operands
    split_kernel<<<(D_H * D_IN + TB - 1) / TB, TB>>>(Winw, Winh, Winl, D_H * D_IN);
    split_kernel<<<(D_OUT * D_H + TB - 1) / TB, TB>>>(headw, Hdh, Hdl, D_OUT * D_H);
    split_kernel<<<(BATCH * D_IN + TB - 1) / TB, TB>>>(x, xh, xl, BATCH * D_IN);

    // spectral-norm scalar -> g_scal[1]
    matvec_t_kernel<<<D_IN / 256, 256>>>(Winw, u, t);
    reduce_t_kernel<<<1, 1024>>>(t, scal);
    matvec_s_kernel<<<64, 256>>>(Winw, t, scal, s);
    reduce_s_kernel<<<1, 1024>>>(s, scal);

    // x_proj = (x @ W_in^T)/sigma + b_in  (bf16 3-pass)
    {
        dim3 grid(D_H / 64, BATCH / 64);
        gemm_mma<0><<<grid, 128, SMEM_BYTES>>>(xh, xl, Winh, Winl, Winb,
                                               xp, scal + 1, D_IN, D_H, D_H);
    }

    // 30 steps x 3 layers on int8 dual-limb IMMA, ping-pong h
    const signed char* Wq1[3] = {W0q1, W1q1, W2q1};
    const signed char* Wq2[3] = {W0q2, W1q2, W2q2};
    const float* bs[3] = {b0, b1, b2};
    float *cur = hA, *nxt = hB;
    signed char *cq1 = hq1A, *cq2 = hq2A, *nq1 = hq1B, *nq2 = hq2B;
    dim3 gstep(D_H / 64, BATCH / 64);
    for (int st = 0; st < STEPS; st++) {
        for (int l = 0; l < 3; l++) {
            gemm_step_i8<<<gstep, 128, I8_SMEM>>>(cq1, cq2, Wq1[l], Wq2[l], bs[l],
                                                  xp, cur, nxt, nq1, nq2);
            float* tf = cur; cur = nxt; nxt = tf;
            signed char* t1 = cq1; cq1 = nq1; nq1 = t1;
            signed char* t2 = cq2; cq2 = nq2; nq2 = t2;
        }
    }

    // final h -> bf16 hi/lo, then head GEMM
    split_kernel<<<(BATCH * D_H + TB - 1) / TB, TB>>>(cur, hh, hl, BATCH * D_H);
    {
        dim3 grid((D_OUT + 63) / 64, BATCH / 64);
        gemm_mma<2><<<grid, 128, SMEM_BYTES>>>(hh, hl, Hdh, Hdl, headb,
                                               out, nullptr, D_H, D_OUT, D_OUT);
    }
}

// round 7
// speedup vs baseline: 2.1663x; 2.1663x over previous
#include <cuda_runtime.h>
#include <cuda_bf16.h>
#include <math.h>
#include <stdint.h>

#define D_IN   1024
#define D_H    2048
#define BATCH  256
#define D_OUT  1000
#define EPSV   1e-12f
#define STEPS  30

// ---- bf16 aux GEMM smem geometry (x_proj / head, 128-thread kernel) ----
#define ROW_B      144
#define TILE_A_HI  0
#define TILE_A_LO  9216
#define TILE_B_HI  18432
#define TILE_B_LO  27648
#define STAGE_BYTES 36864
#define SMEM_BYTES  (2 * STAGE_BYTES)

// ---- step GEMM smem geometry: BK=128, 4 tiles of 64 rows x 256B pad 272 ----
#define SROW    272
#define STILE   (64 * SROW)           // 17408
#define S_AH    0
#define S_AL    17408
#define S_BH    34816
#define S_BL    52224
#define S_STAGE 69632
#define S_SMEM  (2 * S_STAGE)         // 139264

// ---------------- device scratch (no allocations allowed) ----------------
__device__ float g_t[D_IN];
__device__ float g_s[D_H];
__device__ float g_scal[4];            // [1] = 1/sigma
__device__ float g_xproj[BATCH * D_H];
__device__ float g_xpb[3][BATCH * D_H];  // xproj + bias_l, per layer
__device__ float g_hA[BATCH * D_H];
__device__ float g_hB[BATCH * D_H];

__device__ __nv_bfloat16 g_W0hi[D_H * D_H], g_W0lo[D_H * D_H];
__device__ __nv_bfloat16 g_W1hi[D_H * D_H], g_W1lo[D_H * D_H];
__device__ __nv_bfloat16 g_W2hi[D_H * D_H], g_W2lo[D_H * D_H];
__device__ __nv_bfloat16 g_Winhi[D_H * D_IN], g_Winlo[D_H * D_IN];
__device__ __nv_bfloat16 g_Hdhi[D_OUT * D_H], g_Hdlo[D_OUT * D_H];
__device__ __nv_bfloat16 g_xhi[BATCH * D_IN], g_xlo[BATCH * D_IN];
__device__ __nv_bfloat16 g_hhiA[BATCH * D_H], g_hloA[BATCH * D_H];
__device__ __nv_bfloat16 g_hhiB[BATCH * D_H], g_hloB[BATCH * D_H];

// ---------------- portable PTX helpers (sm_80+) ----------------
__device__ __forceinline__ uint32_t smem_u32(const void* p) {
    uint32_t a;
    asm("{ .reg .u64 t; cvta.to.shared.u64 t, %1; cvt.u32.u64 %0, t; }" : "=r"(a) : "l"(p));
    return a;
}
#define CP16(dst, src) asm volatile("cp.async.cg.shared.global [%0], [%1], 16;" :: "r"(dst), "l"(src))
#define CP_COMMIT()    asm volatile("cp.async.commit_group;" ::: "memory")
#define CP_WAIT(n)     asm volatile("cp.async.wait_group %0;" :: "n"(n) : "memory")

__device__ __forceinline__ void ldsm4(uint32_t* r, uint32_t addr) {
    asm volatile("ldmatrix.sync.aligned.m8n8.x4.shared.b16 {%0,%1,%2,%3}, [%4];"
        : "=r"(r[0]), "=r"(r[1]), "=r"(r[2]), "=r"(r[3]) : "r"(addr));
}
__device__ __forceinline__ void mma_bf16(float* c, const uint32_t* a, const uint32_t* b) {
    asm volatile("mma.sync.aligned.m16n8k16.row.col.f32.bf16.bf16.f32 "
        "{%0,%1,%2,%3}, {%4,%5,%6,%7}, {%8,%9}, {%0,%1,%2,%3};"
        : "+f"(c[0]), "+f"(c[1]), "+f"(c[2]), "+f"(c[3])
        : "r"(a[0]), "r"(a[1]), "r"(a[2]), "r"(a[3]), "r"(b[0]), "r"(b[1]));
}

// ---------------- small kernels ----------------
__global__ void zero_kernel(float* p, int n) {
    int i = blockIdx.x * blockDim.x + threadIdx.x;
    if (i < n) p[i] = 0.0f;
}
__global__ void split_kernel(const float* __restrict__ src,
                             __nv_bfloat16* __restrict__ hi,
                             __nv_bfloat16* __restrict__ lo, int n) {
    int i = blockIdx.x * blockDim.x + threadIdx.x;
    if (i >= n) return;
    float a = src[i];
    __nv_bfloat16 h = __float2bfloat16(a);
    hi[i] = h;
    lo[i] = __float2bfloat16(a - __bfloat162float(h));
}
__global__ void add_bias_kernel(const float* __restrict__ xp,
                                const float* __restrict__ b,
                                float* __restrict__ dst, int n) {
    int i = blockIdx.x * blockDim.x + threadIdx.x;
    if (i < n) dst[i] = xp[i] + b[i & (D_H - 1)];
}
__global__ void matvec_t_kernel(const float* __restrict__ W, const float* __restrict__ u,
                                float* __restrict__ t) {
    int j = blockIdx.x * blockDim.x + threadIdx.x;
    if (j >= D_IN) return;
    float acc = 0.0f;
#pragma unroll 4
    for (int i = 0; i < D_H; i++) acc = fmaf(W[(size_t)i * D_IN + j], u[i], acc);
    t[j] = acc;
}
__global__ void reduce_t_kernel(const float* __restrict__ t, float* __restrict__ scal) {
    __shared__ float sh[1024];
    int tid = threadIdx.x;
    float v = t[tid];
    sh[tid] = v * v;
    __syncthreads();
    for (int o = 512; o > 0; o >>= 1) { if (tid < o) sh[tid] += sh[tid + o]; __syncthreads(); }
    if (tid == 0) scal[0] = 1.0f / (sqrtf(sh[0]) + EPSV);
}
__global__ void matvec_s_kernel(const float* __restrict__ W, const float* __restrict__ t,
                                const float* __restrict__ scal, float* __restrict__ s) {
    int gtid = blockIdx.x * blockDim.x + threadIdx.x;
    int warp = gtid >> 5, lane = gtid & 31;
    float invn = scal[0];
    for (int r = warp; r < D_H; r += 512) {
        const float* row = W + (size_t)r * D_IN;
        float acc = 0.0f;
        for (int j = lane; j < D_IN; j += 32) acc = fmaf(row[j], t[j], acc);
#pragma unroll
        for (int o = 16; o > 0; o >>= 1) acc += __shfl_xor_sync(0xffffffffu, acc, o);
        if (lane == 0) s[r] = acc * invn;
    }
}
__global__ void reduce_s_kernel(const float* __restrict__ s, float* __restrict__ scal) {
    __shared__ float sh[1024];
    int tid = threadIdx.x;
    float a = s[tid], b = s[tid + 1024];
    sh[tid] = a * a + b * b;
    __syncthreads();
    for (int o = 512; o > 0; o >>= 1) { if (tid < o) sh[tid] += sh[tid + o]; __syncthreads(); }
    if (tid == 0) { float q = sh[0]; scal[1] = (sqrtf(q) + EPSV) / q; }
}

// ================= bf16 3-pass aux GEMM (x_proj MODE 0, head MODE 2) =================
// (R5-proven 128-thread kernel, used for 2 launches only)
template <int MODE>
__device__ __forceinline__ void epi_elem(float r, int m, int n,
        const float* __restrict__ bias, float* __restrict__ outF,
        float scale, int NB, int ldOut) {
    if (MODE == 0) {
        outF[(size_t)m * ldOut + n] = fmaf(r, scale, bias[n]);
    } else {
        if (n < NB) outF[(size_t)m * ldOut + n] = r + bias[n];
    }
}

__device__ __forceinline__ void prefetch_chunk(uint32_t sb_u, char* sb_p, int k0,
        const __nv_bfloat16* __restrict__ Ahi, const __nv_bfloat16* __restrict__ Alo,
        const __nv_bfloat16* __restrict__ Bhi, const __nv_bfloat16* __restrict__ Blo,
        int K, int NB, int m0, int n0) {
    const int t = threadIdx.x;
#pragma unroll
    for (int r = 0; r < 4; r++) {
        const int idx = t + (r << 7);
        const int row = idx >> 3;
        const int c   = idx & 7;
        const uint32_t soff = (uint32_t)row * ROW_B + (c << 4);
        const size_t ga = (size_t)(m0 + row) * K + k0 + (c << 3);
        CP16(sb_u + TILE_A_HI + soff, Ahi + ga);
        CP16(sb_u + TILE_A_LO + soff, Alo + ga);
        const int gn = n0 + row;
        if (gn < NB) {
            const size_t gb = (size_t)gn * K + k0 + (c << 3);
            CP16(sb_u + TILE_B_HI + soff, Bhi + gb);
            CP16(sb_u + TILE_B_LO + soff, Blo + gb);
        } else {
            const uint4 z = make_uint4(0, 0, 0, 0);
            *reinterpret_cast<uint4*>(sb_p + TILE_B_HI + soff) = z;
            *reinterpret_cast<uint4*>(sb_p + TILE_B_LO + soff) = z;
        }
    }
}

template <int MODE>
__global__ void __launch_bounds__(128)
gemm_mma(const __nv_bfloat16* __restrict__ Ahi, const __nv_bfloat16* __restrict__ Alo,
         const __nv_bfloat16* __restrict__ Bhi, const __nv_bfloat16* __restrict__ Blo,
         const float* __restrict__ bias, float* __restrict__ outF,
         const float* __restrict__ scale_ptr, int K, int NB, int ldOut) {
    extern __shared__ char smem[];
    const uint32_t sbase = smem_u32(smem);
    const int tid  = threadIdx.x;
    const int lane = tid & 31;
    const int wid  = tid >> 5;
    const int m0 = blockIdx.y * 64;
    const int n0 = blockIdx.x * 64;
    const int wm = (wid >> 1) << 5;
    const int wn = (wid & 1) << 5;
    const int NC = K >> 6;

    const int arow  = (lane & 7) | (((lane >> 3) & 1) << 3);
    const int akoff = ((lane >> 4) & 1) << 3;
    const int brow  = (lane & 7) | (((lane >> 4) & 1) << 3);
    const int bkoff = ((lane >> 3) & 1) << 3;

    float acc[2][4][4] = {};

    prefetch_chunk(sbase, smem, 0, Ahi, Alo, Bhi, Blo, K, NB, m0, n0);
    CP_COMMIT();

    for (int c = 0; c < NC; c++) {
        if (c + 1 < NC) {
            const int ns = (c + 1) & 1;
            prefetch_chunk(sbase + ns * STAGE_BYTES, smem + ns * STAGE_BYTES,
                           (c + 1) << 6, Ahi, Alo, Bhi, Blo, K, NB, m0, n0);
            CP_COMMIT();
            CP_WAIT(1);
        } else {
            CP_WAIT(0);
        }
        __syncthreads();

        const uint32_t st = sbase + (c & 1) * STAGE_BYTES;
#pragma unroll
        for (int kk = 0; kk < 4; kk++) {
            const int k0 = kk << 4;
            uint32_t ah[2][4], al[2][4], bh[2][4], bl[2][4];
#pragma unroll
            for (int a = 0; a < 2; a++) {
                const uint32_t off = (uint32_t)(wm + (a << 4) + arow) * ROW_B +
                                     ((k0 + akoff) << 1);
                ldsm4(ah[a], st + TILE_A_HI + off);
                ldsm4(al[a], st + TILE_A_LO + off);
            }
#pragma unroll
            for (int b = 0; b < 2; b++) {
                const uint32_t off = (uint32_t)(wn + (b << 4) + brow) * ROW_B +
                                     ((k0 + bkoff) << 1);
                ldsm4(bh[b], st + TILE_B_HI + off);
                ldsm4(bl[b], st + TILE_B_LO + off);
            }
#pragma unroll
            for (int a = 0; a < 2; a++)
#pragma unroll
                for (int j = 0; j < 4; j++)
                    mma_bf16(acc[a][j], ah[a], &bh[j >> 1][(j & 1) << 1]);
#pragma unroll
            for (int a = 0; a < 2; a++)
#pragma unroll
                for (int j = 0; j < 4; j++)
                    mma_bf16(acc[a][j], ah[a], &bl[j >> 1][(j & 1) << 1]);
#pragma unroll
            for (int a = 0; a < 2; a++)
#pragma unroll
                for (int j = 0; j < 4; j++)
                    mma_bf16(acc[a][j], al[a], &bh[j >> 1][(j & 1) << 1]);
        }
        __syncthreads();
    }

    const float scale = (MODE == 0) ? *scale_ptr : 1.0f;
    const int g  = lane >> 2;
    const int i2 = (lane & 3) << 1;
#pragma unroll
    for (int a = 0; a < 2; a++)
#pragma unroll
        for (int j = 0; j < 4; j++)
#pragma unroll
            for (int e = 0; e < 4; e++) {
                const int m = m0 + wm + (a << 4) + g + ((e >> 1) << 3);
                const int n = n0 + wn + (j << 3) + i2 + (e & 1);
                epi_elem<MODE>(acc[a][j][e], m, n, bias, outF, scale, NB, ldOut);
            }
}

// ================= step GEMM: bf16 3-pass, 256 threads, BK=128 =================
// 8 warps, 64x64 CTA tile, 32x16 warp tile (2 m-warps x 4 n-warps).
// hn = 0.5*hold + 0.5*tanh(xpb + acc); outF=hn; outHi/Lo = bf16 split(hn)
__device__ __forceinline__ void prefetch_step(uint32_t sb_u, int k0,
        const __nv_bfloat16* __restrict__ Ahi, const __nv_bfloat16* __restrict__ Alo,
        const __nv_bfloat16* __restrict__ Bhi, const __nv_bfloat16* __restrict__ Blo,
        int m0, int n0) {
    const int t = threadIdx.x;
#pragma unroll
    for (int r = 0; r < 4; r++) {
        const int idx = t + (r << 8);          // 0..1023
        const int row = idx >> 4;              // 0..63
        const int c   = idx & 15;              // 16B units, 256B row
        const uint32_t soff = (uint32_t)row * SROW + (c << 4);
        const size_t ga = (size_t)(m0 + row) * D_H + k0 + (c << 3);
        const size_t gb = (size_t)(n0 + row) * D_H + k0 + (c << 3);
        CP16(sb_u + S_AH + soff, Ahi + ga);
        CP16(sb_u + S_AL + soff, Alo + ga);
        CP16(sb_u + S_BH + soff, Bhi + gb);
        CP16(sb_u + S_BL + soff, Blo + gb);
    }
}

__global__ void __launch_bounds__(256)
gemm_step(const __nv_bfloat16* __restrict__ Ahi, const __nv_bfloat16* __restrict__ Alo,
          const __nv_bfloat16* __restrict__ Bhi, const __nv_bfloat16* __restrict__ Blo,
          const float* __restrict__ xpb, const float* __restrict__ hold,
          float* __restrict__ outF,
          __nv_bfloat16* __restrict__ outHi, __nv_bfloat16* __restrict__ outLo) {
    extern __shared__ char smem[];
    const uint32_t sbase = smem_u32(smem);
    const int tid  = threadIdx.x;
    const int lane = tid & 31;
    const int wid  = tid >> 5;
    const int m0 = blockIdx.y * 64;
    const int n0 = blockIdx.x * 64;
    const int wm = (wid >> 2) << 5;   // 0 or 32
    const int wn = (wid & 3) << 4;    // 0,16,32,48
    const int NC = D_H >> 7;          // 16 chunks of 128

    const int arow  = (lane & 7) | (((lane >> 3) & 1) << 3);
    const int akoff = ((lane >> 4) & 1) << 3;
    const int brow  = (lane & 7) | (((lane >> 4) & 1) << 3);
    const int bkoff = ((lane >> 3) & 1) << 3;

    float accm[2][2][4] = {};   // main: ah*bh
    float accc[2][2][4] = {};   // corrections: ah*bl + al*bh

    prefetch_step(sbase, 0, Ahi, Alo, Bhi, Blo, m0, n0);
    CP_COMMIT();

    for (int c = 0; c < NC; c++) {
        if (c + 1 < NC) {
            const int ns = (c + 1) & 1;
            prefetch_step(sbase + ns * S_STAGE, (c + 1) << 7, Ahi, Alo, Bhi, Blo, m0, n0);
            CP_COMMIT();
            CP_WAIT(1);
        } else {
            CP_WAIT(0);
        }
        __syncthreads();

        const uint32_t st = sbase + (c & 1) * S_STAGE;
#pragma unroll
        for (int kk = 0; kk < 8; kk++) {
            const int k0 = kk << 4;
            uint32_t ah[2][4], al[2][4], bh[4], bl[4];
#pragma unroll
            for (int a = 0; a < 2; a++) {
                const uint32_t off = (uint32_t)(wm + (a << 4) + arow) * SROW +
                                     ((k0 + akoff) << 1);
                ldsm4(ah[a], st + S_AH + off);
                ldsm4(al[a], st + S_AL + off);
            }
            {
                const uint32_t off = (uint32_t)(wn + brow) * SROW + ((k0 + bkoff) << 1);
                ldsm4(bh, st + S_BH + off);
                ldsm4(bl, st + S_BL + off);
            }
#pragma unroll
            for (int a = 0; a < 2; a++)
#pragma unroll
                for (int j = 0; j < 2; j++)
                    mma_bf16(accm[a][j], ah[a], &bh[j << 1]);
#pragma unroll
            for (int a = 0; a < 2; a++)
#pragma unroll
                for (int j = 0; j < 2; j++)
                    mma_bf16(accc[a][j], ah[a], &bl[j << 1]);
#pragma unroll
            for (int a = 0; a < 2; a++)
#pragma unroll
                for (int j = 0; j < 2; j++)
                    mma_bf16(accc[a][j], al[a], &bh[j << 1]);
        }
        __syncthreads();
    }

    // epilogue: vectorized 2-wide (n even pairs)
    const int g  = lane >> 2;
    const int i2 = (lane & 3) << 1;
#pragma unroll
    for (int a = 0; a < 2; a++)
#pragma unroll
        for (int j = 0; j < 2; j++)
#pragma unroll
            for (int eh = 0; eh < 2; eh++) {   // row halves: e={0,1} then e={2,3}
                const int m = m0 + wm + (a << 4) + g + (eh << 3);
                const int n = n0 + wn + (j << 3) + i2;
                const size_t idx = (size_t)m * D_H + n;
                const float r0 = accm[a][j][eh * 2 + 0] + accc[a][j][eh * 2 + 0];
                const float r1 = accm[a][j][eh * 2 + 1] + accc[a][j][eh * 2 + 1];
                const float2 xb = *reinterpret_cast<const float2*>(xpb + idx);
                const float2 ho = *reinterpret_cast<const float2*>(hold + idx);
                const float hn0 = 0.5f * ho.x + 0.5f * tanhf(xb.x + r0);
                const float hn1 = 0.5f * ho.y + 0.5f * tanhf(xb.y + r1);
                *reinterpret_cast<float2*>(outF + idx) = make_float2(hn0, hn1);
                const __nv_bfloat16 b0 = __float2bfloat16(hn0);
                const __nv_bfloat16 b1 = __float2bfloat16(hn1);
                __nv_bfloat162 hiv, lov;
                hiv.x = b0; hiv.y = b1;
                lov.x = __float2bfloat16(hn0 - __bfloat162float(b0));
                lov.y = __float2bfloat16(hn1 - __bfloat162float(b1));
                *reinterpret_cast<__nv_bfloat162*>(outHi + idx) = hiv;
                *reinterpret_cast<__nv_bfloat162*>(outLo + idx) = lov;
            }
}

// ---------------- host ----------------
extern "C" void kernel_launch(void* const* d_in, const int* in_sizes, int n_in,
                              void* d_out, int out_size) {
    const float* x     = (const float*)d_in[0];
    const float* Winw  = (const float*)d_in[1];
    const float* Winb  = (const float*)d_in[2];
    const float* u     = (const float*)d_in[3];
    const float* W0    = (const float*)d_in[4];
    const float* b0    = (const float*)d_in[5];
    const float* W1    = (const float*)d_in[6];
    const float* b1    = (const float*)d_in[7];
    const float* W2    = (const float*)d_in[8];
    const float* b2    = (const float*)d_in[9];
    const float* headw = (const float*)d_in[10];
    const float* headb = (const float*)d_in[11];
    float* out = (float*)d_out;

    float *t, *s, *scal, *xp, *hA, *hB, *xpb;
    cudaGetSymbolAddress((void**)&t, g_t);
    cudaGetSymbolAddress((void**)&s, g_s);
    cudaGetSymbolAddress((void**)&scal, g_scal);
    cudaGetSymbolAddress((void**)&xp, g_xproj);
    cudaGetSymbolAddress((void**)&xpb, g_xpb);
    cudaGetSymbolAddress((void**)&hA, g_hA);
    cudaGetSymbolAddress((void**)&hB, g_hB);
    __nv_bfloat16 *W0h, *W0l, *W1h, *W1l, *W2h, *W2l, *Winh, *Winl, *Hdh, *Hdl;
    __nv_bfloat16 *xh, *xl, *hhA, *hlA, *hhB, *hlB;
    cudaGetSymbolAddress((void**)&W0h, g_W0hi);  cudaGetSymbolAddress((void**)&W0l, g_W0lo);
    cudaGetSymbolAddress((void**)&W1h, g_W1hi);  cudaGetSymbolAddress((void**)&W1l, g_W1lo);
    cudaGetSymbolAddress((void**)&W2h, g_W2hi);  cudaGetSymbolAddress((void**)&W2l, g_W2lo);
    cudaGetSymbolAddress((void**)&Winh, g_Winhi); cudaGetSymbolAddress((void**)&Winl, g_Winlo);
    cudaGetSymbolAddress((void**)&Hdh, g_Hdhi);  cudaGetSymbolAddress((void**)&Hdl, g_Hdlo);
    cudaGetSymbolAddress((void**)&xh, g_xhi);    cudaGetSymbolAddress((void**)&xl, g_xlo);
    cudaGetSymbolAddress((void**)&hhA, g_hhiA);  cudaGetSymbolAddress((void**)&hlA, g_hloA);
    cudaGetSymbolAddress((void**)&hhB, g_hhiB);  cudaGetSymbolAddress((void**)&hlB, g_hloB);

    cudaFuncSetAttribute(gemm_mma<0>, cudaFuncAttributeMaxDynamicSharedMemorySize, SMEM_BYTES);
    cudaFuncSetAttribute(gemm_mma<2>, cudaFuncAttributeMaxDynamicSharedMemorySize, SMEM_BYTES);
    cudaFuncSetAttribute(gemm_step, cudaFuncAttributeMaxDynamicSharedMemorySize, S_SMEM);

    // h0 = 0 (fp32 + bf16 hi/lo views)
    zero_kernel<<<(BATCH * D_H + 255) / 256, 256>>>(hA, BATCH * D_H);
    zero_kernel<<<(BATCH * D_H / 2 + 255) / 256, 256>>>((float*)hhA, BATCH * D_H / 2);
    zero_kernel<<<(BATCH * D_H / 2 + 255) / 256, 256>>>((float*)hlA, BATCH * D_H / 2);

    // hi/lo splits of static operands
    const int TB = 256;
    split_kernel<<<(D_H * D_H + TB - 1) / TB, TB>>>(W0, W0h, W0l, D_H * D_H);
    split_kernel<<<(D_H * D_H + TB - 1) / TB, TB>>>(W1, W1h, W1l, D_H * D_H);
    split_kernel<<<(D_H * D_H + TB - 1) / TB, TB>>>(W2, W2h, W2l, D_H * D_H);
    split_kernel<<<(D_H * D_IN + TB - 1) / TB, TB>>>(Winw, Winh, Winl, D_H * D_IN);
    split_kernel<<<(D_OUT * D_H + TB - 1) / TB, TB>>>(headw, Hdh, Hdl, D_OUT * D_H);
    split_kernel<<<(BATCH * D_IN + TB - 1) / TB, TB>>>(x, xh, xl, BATCH * D_IN);

    // spectral-norm scalar -> g_scal[1]
    matvec_t_kernel<<<D_IN / 256, 256>>>(Winw, u, t);
    reduce_t_kernel<<<1, 1024>>>(t, scal);
    matvec_s_kernel<<<64, 256>>>(Winw, t, scal, s);
    reduce_s_kernel<<<1, 1024>>>(s, scal);

    // x_proj = (x @ W_in^T)/sigma + b_in
    {
        dim3 grid(D_H / 64, BATCH / 64);
        gemm_mma<0><<<grid, 128, SMEM_BYTES>>>(xh, xl, Winh, Winl, Winb,
                                               xp, scal + 1, D_IN, D_H, D_H);
    }
    // xpb_l = xproj + b_l (fold per-layer bias once)
    const float* bs[3] = {b0, b1, b2};
    for (int l = 0; l < 3; l++)
        add_bias_kernel<<<(BATCH * D_H + TB - 1) / TB, TB>>>(
            xp, bs[l], xpb + (size_t)l * BATCH * D_H, BATCH * D_H);

    // 30 steps x 3 layers
    const __nv_bfloat16* Wh[3] = {W0h, W1h, W2h};
    const __nv_bfloat16* Wl[3] = {W0l, W1l, W2l};
    float *cur = hA, *nxt = hB;
    __nv_bfloat16 *curh = hhA, *curl = hlA, *nxth = hhB, *nxtl = hlB;
    dim3 gstep(D_H / 64, BATCH / 64);
    for (int st = 0; st < STEPS; st++) {
        for (int l = 0; l < 3; l++) {
            gemm_step<<<gstep, 256, S_SMEM>>>(curh, curl, Wh[l], Wl[l],
                                              xpb + (size_t)l * BATCH * D_H,
                                              cur, nxt, nxth, nxtl);
            float* tf = cur; cur = nxt; nxt = tf;
            __nv_bfloat16* th = curh; curh = nxth; nxth = th;
            __nv_bfloat16* tl = curl; curl = nxtl; nxtl = tl;
        }
    }

    // head: out = h @ head_w^T + head_b
    {
        dim3 grid((D_OUT + 63) / 64, BATCH / 64);
        gemm_mma<2><<<grid, 128, SMEM_BYTES>>>(curh, curl, Hdh, Hdl, headb,
                                               out, nullptr, D_H, D_OUT, D_OUT);
    }
}